// round 15
// baseline (speedup 1.0000x reference)
#include <cuda_runtime.h>
#include <cuda_fp16.h>
#include <math.h>
#include <stdint.h>

// Problem constants
#define HID   2048
#define NH    16
#define NKV   4
#define HD    128
#define SEQ   1024
#define NB    4
#define NT    4096
#define QKV_N 3072
#define FFI   8192
#define EPS   1e-6f
#define NEGF  (-1e30f)

// ---------------- scratch ----------------
__device__ __half g_hH   [(size_t)NT * HID];
__device__ float  g_qkv  [(size_t)NT * QKV_N];
__device__ __half g_aoutH[(size_t)NT * HID];
__device__ float  g_h1   [(size_t)NT * HID];
__device__ __half g_h2H  [(size_t)NT * HID];
__device__ __half g_guH  [(size_t)NT * 2 * FFI];
__device__ __half g_actH [(size_t)NT * FFI];
__device__ __half g_wqkvH[(size_t)HID * QKV_N];
__device__ __half g_woH  [(size_t)HID * HID];
__device__ __half g_wguH [(size_t)HID * 2 * FFI];
__device__ __half g_wdnH [(size_t)FFI * HID];

// ---------------- helpers ----------------
__device__ __forceinline__ void cp_async16(void* s, const void* g) {
    uint32_t sa = (uint32_t)__cvta_generic_to_shared(s);
    asm volatile("cp.async.cg.shared.global [%0], [%1], 16;\n" :: "r"(sa), "l"(g));
}
__device__ __forceinline__ void ldmx4(uint32_t* r, uint32_t a) {
    asm volatile("ldmatrix.sync.aligned.m8n8.x4.shared.b16 {%0,%1,%2,%3}, [%4];"
        : "=r"(r[0]), "=r"(r[1]), "=r"(r[2]), "=r"(r[3]) : "r"(a));
}
__device__ __forceinline__ void ldmx4t(uint32_t* r, uint32_t a) {
    asm volatile("ldmatrix.sync.aligned.m8n8.x4.trans.shared.b16 {%0,%1,%2,%3}, [%4];"
        : "=r"(r[0]), "=r"(r[1]), "=r"(r[2]), "=r"(r[3]) : "r"(a));
}
__device__ __forceinline__ void mma_f16(float* d, const uint32_t* a, const uint32_t* b) {
    asm volatile(
        "mma.sync.aligned.m16n8k16.row.col.f32.f16.f16.f32 "
        "{%0,%1,%2,%3}, {%4,%5,%6,%7}, {%8,%9}, {%0,%1,%2,%3};\n"
        : "+f"(d[0]), "+f"(d[1]), "+f"(d[2]), "+f"(d[3])
        : "r"(a[0]), "r"(a[1]), "r"(a[2]), "r"(a[3]), "r"(b[0]), "r"(b[1]));
}

// ---------------- fp32 -> fp16 weight copy ----------------
__global__ void __launch_bounds__(256) h2fcopy_kernel(const float* __restrict__ s,
                                                      __half* __restrict__ d) {
    const size_t i = ((size_t)blockIdx.x * 256 + threadIdx.x) * 4;
    const float4 v = *(const float4*)(s + i);
    __half2 p0 = __floats2half2_rn(v.x, v.y);
    __half2 p1 = __floats2half2_rn(v.z, v.w);
    uint2 pk = make_uint2(*(uint32_t*)&p0, *(uint32_t*)&p1);
    *(uint2*)(d + i) = pk;
}

// ---------------- FP16 tensor-core GEMM (3-stage pipeline) ----------------
// C[M,N] = A[M,K] @ B[K,N].  EPI: 0 = fp32 out, 1 = fp32 out + residual, 2 = half out.
// 3-stage cp.async ring: one __syncthreads per K-tile (prefetch at iter t targets
// buffer (t+2)%3 == (t-1)%3, whose readers all passed the top-of-loop barrier).
#define APITCH 40
#define BPITCH 136
#define ABUF (128 * APITCH)
#define BBUF (32 * BPITCH)
#define GEMM_SMEM (3 * (ABUF + BBUF) * 2)

template <int EPI>
__global__ void __launch_bounds__(256, 2) f16gemm_kernel(const __half* __restrict__ A,
                                                         const __half* __restrict__ B,
                                                         const float* __restrict__ R,
                                                         void* __restrict__ Cv,
                                                         int M, int N, int K) {
    extern __shared__ __half sh[];
    __half* AsB = sh;                 // [3][ABUF]
    __half* BsB = sh + 3 * ABUF;      // [3][BBUF]

    const int tid  = threadIdx.x;
    const int bm   = blockIdx.y * 128;
    const int bn   = blockIdx.x * 128;
    const int lane = tid & 31;
    const int warp = tid >> 5;
    const int g = lane >> 2;
    const int c = lane & 3;
    const int wm = (warp >> 2) * 64;
    const int wn = (warp & 3) * 32;

    float acc[4][4][4];
#pragma unroll
    for (int mi = 0; mi < 4; mi++)
#pragma unroll
        for (int ni = 0; ni < 4; ni++)
#pragma unroll
            for (int r = 0; r < 4; r++) acc[mi][ni][r] = 0.0f;

    const int ntiles = K >> 5;

    auto load_tile = [&](int t, int b) {
        __half* Ab = AsB + b * ABUF;
        __half* Bb = BsB + b * BBUF;
        const int kof = t << 5;
#pragma unroll
        for (int j = 0; j < 2; j++) {
            const int ca = tid + j * 256;
            const int row = ca >> 2, kc = ca & 3;
            cp_async16(&Ab[row * APITCH + kc * 8],
                       A + (size_t)(bm + row) * K + kof + kc * 8);
        }
#pragma unroll
        for (int j = 0; j < 2; j++) {
            const int cb = tid + j * 256;
            const int row = cb >> 4, nc = cb & 15;
            cp_async16(&Bb[row * BPITCH + nc * 8],
                       B + (size_t)(kof + row) * N + bn + nc * 8);
        }
        asm volatile("cp.async.commit_group;\n");
    };

    load_tile(0, 0);
    load_tile(1, 1);

    const int aq = lane >> 3;
    const int arow = (lane & 7) + (aq & 1) * 8;
    const int acol = (aq >> 1) * 8;
    const int bkrow = (aq & 1) * 8 + (lane & 7);
    const int bncol = (aq >> 1) * 8;

    for (int t = 0; t < ntiles; t++) {
        if (t + 1 < ntiles) asm volatile("cp.async.wait_group 1;\n");
        else                asm volatile("cp.async.wait_group 0;\n");
        __syncthreads();
        if (t + 2 < ntiles) load_tile(t + 2, (t + 2) % 3);

        const int buf = t % 3;
        const uint32_t baseA = (uint32_t)__cvta_generic_to_shared(AsB + buf * ABUF);
        const uint32_t baseB = (uint32_t)__cvta_generic_to_shared(BsB + buf * BBUF);

#pragma unroll
        for (int ks = 0; ks < 2; ks++) {
            const int k0 = ks << 4;
            uint32_t af[4][4], bf[2][4];
#pragma unroll
            for (int mi = 0; mi < 4; mi++) {
                const int row = wm + mi * 16 + arow;
                ldmx4(af[mi], baseA + (uint32_t)(row * APITCH + k0 + acol) * 2);
            }
#pragma unroll
            for (int n2 = 0; n2 < 2; n2++) {
                const int kk = k0 + bkrow;
                const int nn = wn + n2 * 16 + bncol;
                ldmx4t(bf[n2], baseB + (uint32_t)(kk * BPITCH + nn) * 2);
            }
#pragma unroll
            for (int mi = 0; mi < 4; mi++)
#pragma unroll
                for (int ni = 0; ni < 4; ni++)
                    mma_f16(acc[mi][ni], af[mi], &bf[ni >> 1][(ni & 1) * 2]);
        }
        // no trailing sync: next iteration's top barrier guards buffer reuse
    }

#pragma unroll
    for (int mi = 0; mi < 4; mi++) {
#pragma unroll
        for (int ni = 0; ni < 4; ni++) {
            const int row = bm + wm + mi * 16 + g;
            const int col = bn + wn + ni * 8 + 2 * c;
            const size_t o0 = (size_t)row * N + col;
            const size_t o1 = (size_t)(row + 8) * N + col;
            if (EPI == 2) {
                __half* Ch = (__half*)Cv;
                *(__half2*)(Ch + o0) = __floats2half2_rn(acc[mi][ni][0], acc[mi][ni][1]);
                *(__half2*)(Ch + o1) = __floats2half2_rn(acc[mi][ni][2], acc[mi][ni][3]);
            } else {
                float* C = (float*)Cv;
                float2 v0 = make_float2(acc[mi][ni][0], acc[mi][ni][1]);
                float2 v1 = make_float2(acc[mi][ni][2], acc[mi][ni][3]);
                if (EPI == 1) {
                    float2 r0 = *(const float2*)(R + o0);
                    float2 r1 = *(const float2*)(R + o1);
                    v0.x += r0.x; v0.y += r0.y;
                    v1.x += r1.x; v1.y += r1.y;
                }
                *(float2*)(C + o0) = v0;
                *(float2*)(C + o1) = v1;
            }
        }
    }
}

// ---------------- RMSNorm (fp32 in, half out) ----------------
__global__ void __launch_bounds__(256) rmsnorm_kernel(const float* __restrict__ x,
                                                      const float* __restrict__ w,
                                                      __half* __restrict__ out) {
    const int row = blockIdx.x;
    const int tid = threadIdx.x;
    const float4* xr = (const float4*)(x + (size_t)row * HID);
    const float4* wr = (const float4*)w;

    float4 v0 = xr[tid];
    float4 v1 = xr[tid + 256];
    float ss = v0.x*v0.x + v0.y*v0.y + v0.z*v0.z + v0.w*v0.w
             + v1.x*v1.x + v1.y*v1.y + v1.z*v1.z + v1.w*v1.w;

    __shared__ float red[256];
    red[tid] = ss;
    __syncthreads();
    for (int s = 128; s > 0; s >>= 1) {
        if (tid < s) red[tid] += red[tid + s];
        __syncthreads();
    }
    const float inv = rsqrtf(red[0] * (1.0f / HID) + EPS);

    float4 w0 = wr[tid], w1 = wr[tid + 256];
    __half2* oh = (__half2*)(out + (size_t)row * HID);
    oh[tid * 2]           = __floats2half2_rn(v0.x*inv*w0.x, v0.y*inv*w0.y);
    oh[tid * 2 + 1]       = __floats2half2_rn(v0.z*inv*w0.z, v0.w*inv*w0.w);
    oh[512 + tid * 2]     = __floats2half2_rn(v1.x*inv*w1.x, v1.y*inv*w1.y);
    oh[512 + tid * 2 + 1] = __floats2half2_rn(v1.z*inv*w1.z, v1.w*inv*w1.w);
}

// ---------------- RoPE (fp32 qkv, in place) ----------------
__global__ void rope_kernel(float* __restrict__ qkv, const int* __restrict__ pos) {
    const int t  = blockIdx.x;
    const int hh = blockIdx.y;
    const int i  = threadIdx.x;
    const float p = (float)pos[t & (SEQ - 1)];
    const float inv_freq = powf(10000.0f, -((float)i) / 64.0f);
    float sn, cs;
    sincosf(p * inv_freq, &sn, &cs);
    float* vp = qkv + (size_t)t * QKV_N + hh * HD;
    const float t1 = vp[i];
    const float t2 = vp[i + 64];
    vp[i]      = t1 * cs - t2 * sn;
    vp[i + 64] = t2 * cs + t1 * sn;
}

// ---------------- Flash attention (fp16 tensor-core, fp32 softmax) ----------------
#define QP 136
#define KP 72
#define VP 136
#define PP 72
#define ATT_SMEM ((64*QP + 128*KP + 64*VP + 64*PP) * 2 + (64*64 + 3*64) * 4)

__global__ void __launch_bounds__(256) attn_kernel(const float* __restrict__ qkv,
                                                   __half* __restrict__ aout) {
    const int qt = blockIdx.x, h = blockIdx.y, b = blockIdx.z;
    const int kvh = h >> 2;

    extern __shared__ char smb[];
    __half* Qh = (__half*)smb;
    __half* Kh = Qh + 64 * QP;
    __half* Vh = Kh + 128 * KP;
    __half* Ph = Vh + 64 * VP;
    float* Ss   = (float*)(Ph + 64 * PP);
    float* rowm = Ss + 64 * 64;
    float* rowl = rowm + 64;
    float* rowa = rowl + 64;

    const int tid  = threadIdx.x;
    const int lane = tid & 31;
    const int warp = tid >> 5;
    const int wr = warp >> 1, wc = warp & 1;
    const int g = lane >> 2, c = lane & 3;
    const int aq = lane >> 3;
    const int arow = (lane & 7) + (aq & 1) * 8;
    const int acol = (aq >> 1) * 8;
    const int bkrow = (aq & 1) * 8 + (lane & 7);
    const int bncol = (aq >> 1) * 8;
    const int q0 = qt * 64;

    const uint32_t baseQ = (uint32_t)__cvta_generic_to_shared(Qh);
    const uint32_t baseK = (uint32_t)__cvta_generic_to_shared(Kh);
    const uint32_t baseV = (uint32_t)__cvta_generic_to_shared(Vh);
    const uint32_t baseP = (uint32_t)__cvta_generic_to_shared(Ph);

    // load Q tile (fp32 -> half)
    for (int i = tid; i < 64 * 32; i += 256) {
        const int r = i >> 5, c4 = i & 31;
        float4 q = *(const float4*)(qkv + (size_t)(b * SEQ + q0 + r) * QKV_N + h * HD + c4 * 4);
        __half2 p0 = __floats2half2_rn(q.x, q.y);
        __half2 p1 = __floats2half2_rn(q.z, q.w);
        *(uint2*)&Qh[r * QP + c4 * 4] = make_uint2(*(uint32_t*)&p0, *(uint32_t*)&p1);
    }
    if (tid < 64) { rowm[tid] = NEGF; rowl[tid] = 0.0f; }

    float oacc[8][4];
#pragma unroll
    for (int ni = 0; ni < 8; ni++)
#pragma unroll
        for (int r = 0; r < 4; r++) oacc[ni][r] = 0.0f;
    __syncthreads();

    const float scale = 0.0883883476483184f;

    for (int kt = 0; kt <= qt; kt++) {
        const int k0 = kt * 64;
        // K tile: transpose to [d][n] halfs
        for (int i = tid; i < 2048; i += 256) {
            const int r = i & 63, c4 = i >> 6;
            float4 kk = *(const float4*)(qkv + (size_t)(b * SEQ + k0 + r) * QKV_N
                                         + NH * HD + kvh * HD + c4 * 4);
            const int d0 = c4 * 4;
            Kh[(d0 + 0) * KP + r] = __float2half_rn(kk.x);
            Kh[(d0 + 1) * KP + r] = __float2half_rn(kk.y);
            Kh[(d0 + 2) * KP + r] = __float2half_rn(kk.z);
            Kh[(d0 + 3) * KP + r] = __float2half_rn(kk.w);
        }
        // V tile: [kv][d] halfs
        for (int i = tid; i < 2048; i += 256) {
            const int r = i >> 5, c4 = i & 31;
            float4 vv = *(const float4*)(qkv + (size_t)(b * SEQ + k0 + r) * QKV_N
                                         + (NH + NKV) * HD + kvh * HD + c4 * 4);
            __half2 p0 = __floats2half2_rn(vv.x, vv.y);
            __half2 p1 = __floats2half2_rn(vv.z, vv.w);
            *(uint2*)&Vh[r * VP + c4 * 4] = make_uint2(*(uint32_t*)&p0, *(uint32_t*)&p1);
        }
        __syncthreads();

        // S = Q @ K^T
        float sacc[4][4];
#pragma unroll
        for (int ni = 0; ni < 4; ni++)
#pragma unroll
            for (int r = 0; r < 4; r++) sacc[ni][r] = 0.0f;

#pragma unroll
        for (int k16 = 0; k16 < 8; k16++) {
            uint32_t af[4], bf[2][4];
            ldmx4(af, baseQ + (uint32_t)((wr * 16 + arow) * QP + k16 * 16 + acol) * 2);
#pragma unroll
            for (int n2 = 0; n2 < 2; n2++)
                ldmx4t(bf[n2], baseK + (uint32_t)((k16 * 16 + bkrow) * KP
                                                  + wc * 32 + n2 * 16 + bncol) * 2);
#pragma unroll
            for (int ni = 0; ni < 4; ni++)
                mma_f16(sacc[ni], af, &bf[ni >> 1][(ni & 1) * 2]);
        }

        const bool diag = (kt == qt);
        const int srow0 = wr * 16 + g;
#pragma unroll
        for (int ni = 0; ni < 4; ni++) {
            const int col = wc * 32 + ni * 8 + 2 * c;
            float v0 = sacc[ni][0] * scale;
            float v1 = sacc[ni][1] * scale;
            float v2 = sacc[ni][2] * scale;
            float v3 = sacc[ni][3] * scale;
            if (diag) {
                if (srow0 < col)           v0 = NEGF;
                if (srow0 < col + 1)       v1 = NEGF;
                if (srow0 + 8 < col)       v2 = NEGF;
                if (srow0 + 8 < col + 1)   v3 = NEGF;
            }
            Ss[srow0 * 64 + col]           = v0;
            Ss[srow0 * 64 + col + 1]       = v1;
            Ss[(srow0 + 8) * 64 + col]     = v2;
            Ss[(srow0 + 8) * 64 + col + 1] = v3;
        }
        __syncthreads();

        // online softmax: exp written directly to Ph (half)
        {
            const int row = tid >> 2, l4 = tid & 3;
            float mx = NEGF;
            for (int cc = l4; cc < 64; cc += 4) mx = fmaxf(mx, Ss[row * 64 + cc]);
            mx = fmaxf(mx, __shfl_xor_sync(0xffffffffu, mx, 1));
            mx = fmaxf(mx, __shfl_xor_sync(0xffffffffu, mx, 2));
            const float mold = rowm[row];
            const float mnew = fmaxf(mold, mx);
            float ls = 0.0f;
            for (int cc = l4; cc < 64; cc += 4) {
                float p = expf(Ss[row * 64 + cc] - mnew);
                Ph[row * PP + cc] = __float2half_rn(p);
                ls += p;
            }
            ls += __shfl_xor_sync(0xffffffffu, ls, 1);
            ls += __shfl_xor_sync(0xffffffffu, ls, 2);
            if (l4 == 0) {
                const float alpha = expf(mold - mnew);
                rowa[row] = alpha;
                rowl[row] = rowl[row] * alpha + ls;
                rowm[row] = mnew;
            }
        }
        __syncthreads();

        // O rescale + O += P @ V
        const float al0 = rowa[wr * 16 + g];
        const float al1 = rowa[wr * 16 + g + 8];
#pragma unroll
        for (int ni = 0; ni < 8; ni++) {
            oacc[ni][0] *= al0; oacc[ni][1] *= al0;
            oacc[ni][2] *= al1; oacc[ni][3] *= al1;
        }

#pragma unroll
        for (int k16 = 0; k16 < 4; k16++) {
            uint32_t af[4], bf[4][4];
            ldmx4(af, baseP + (uint32_t)((wr * 16 + arow) * PP + k16 * 16 + acol) * 2);
#pragma unroll
            for (int n2 = 0; n2 < 4; n2++)
                ldmx4t(bf[n2], baseV + (uint32_t)((k16 * 16 + bkrow) * VP
                                                  + wc * 64 + n2 * 16 + bncol) * 2);
#pragma unroll
            for (int ni = 0; ni < 8; ni++)
                mma_f16(oacc[ni], af, &bf[ni >> 1][(ni & 1) * 2]);
        }
        __syncthreads();
    }

    // normalize & write
    const float il0 = 1.0f / rowl[wr * 16 + g];
    const float il1 = 1.0f / rowl[wr * 16 + g + 8];
    const size_t r0g = (size_t)(b * SEQ + q0 + wr * 16 + g) * HID + h * HD;
    const size_t r1g = (size_t)(b * SEQ + q0 + wr * 16 + g + 8) * HID + h * HD;
#pragma unroll
    for (int ni = 0; ni < 8; ni++) {
        const int col = wc * 64 + ni * 8 + 2 * c;
        *(__half2*)(aout + r0g + col) = __floats2half2_rn(oacc[ni][0] * il0, oacc[ni][1] * il0);
        *(__half2*)(aout + r1g + col) = __floats2half2_rn(oacc[ni][2] * il1, oacc[ni][3] * il1);
    }
}

// ---------------- SiLU(gate)*up (half in, half out) ----------------
__global__ void __launch_bounds__(256) silu_kernel(const __half* __restrict__ gu,
                                                   __half* __restrict__ act) {
    size_t idx = (size_t)blockIdx.x * 256 + threadIdx.x;
    int row = (int)(idx / (FFI / 4));
    int c   = (int)(idx % (FFI / 4));
    uint2 graw = *(const uint2*)(gu + (size_t)row * 2 * FFI + c * 4);
    uint2 uraw = *(const uint2*)(gu + (size_t)row * 2 * FFI + FFI + c * 4);
    float2 g0 = __half22float2(*(__half2*)&graw.x);
    float2 g1 = __half22float2(*(__half2*)&graw.y);
    float2 u0 = __half22float2(*(__half2*)&uraw.x);
    float2 u1 = __half22float2(*(__half2*)&uraw.y);
    float rx = g0.x / (1.0f + expf(-g0.x)) * u0.x;
    float ry = g0.y / (1.0f + expf(-g0.y)) * u0.y;
    float rz = g1.x / (1.0f + expf(-g1.x)) * u1.x;
    float rw = g1.y / (1.0f + expf(-g1.y)) * u1.y;
    __half2 p0 = __floats2half2_rn(rx, ry);
    __half2 p1 = __floats2half2_rn(rz, rw);
    *(uint2*)(act + (size_t)row * FFI + c * 4) = make_uint2(*(uint32_t*)&p0, *(uint32_t*)&p1);
}

// ---------------- launch ----------------
extern "C" void kernel_launch(void* const* d_in, const int* in_sizes, int n_in,
                              void* d_out, int out_size) {
    const float* x    = (const float*)d_in[0];
    const float* ln1w = (const float*)d_in[1];
    const float* wqkv = (const float*)d_in[2];
    const float* wo   = (const float*)d_in[3];
    const float* ln2w = (const float*)d_in[4];
    const float* wgu  = (const float*)d_in[5];
    const float* wdn  = (const float*)d_in[6];
    const int*   pos  = (const int*)d_in[7];
    float* out = (float*)d_out;

    void *phH, *pqkv, *paoH, *ph1, *ph2H, *pgu, *pactH, *pwq, *pwo, *pwg, *pwd;
    cudaGetSymbolAddress(&phH,   g_hH);
    cudaGetSymbolAddress(&pqkv,  g_qkv);
    cudaGetSymbolAddress(&paoH,  g_aoutH);
    cudaGetSymbolAddress(&ph1,   g_h1);
    cudaGetSymbolAddress(&ph2H,  g_h2H);
    cudaGetSymbolAddress(&pgu,   g_guH);
    cudaGetSymbolAddress(&pactH, g_actH);
    cudaGetSymbolAddress(&pwq,   g_wqkvH);
    cudaGetSymbolAddress(&pwo,   g_woH);
    cudaGetSymbolAddress(&pwg,   g_wguH);
    cudaGetSymbolAddress(&pwd,   g_wdnH);
    __half* hH    = (__half*)phH;
    float*  qkv   = (float*)pqkv;
    __half* aoutH = (__half*)paoH;
    float*  h1    = (float*)ph1;
    __half* h2H   = (__half*)ph2H;
    __half* guH   = (__half*)pgu;
    __half* actH  = (__half*)pactH;
    __half* wqkvH = (__half*)pwq;
    __half* woH   = (__half*)pwo;
    __half* wguH  = (__half*)pwg;
    __half* wdnH  = (__half*)pwd;

    cudaFuncSetAttribute(attn_kernel, cudaFuncAttributeMaxDynamicSharedMemorySize, ATT_SMEM);
    cudaFuncSetAttribute(f16gemm_kernel<0>, cudaFuncAttributeMaxDynamicSharedMemorySize, GEMM_SMEM);
    cudaFuncSetAttribute(f16gemm_kernel<1>, cudaFuncAttributeMaxDynamicSharedMemorySize, GEMM_SMEM);
    cudaFuncSetAttribute(f16gemm_kernel<2>, cudaFuncAttributeMaxDynamicSharedMemorySize, GEMM_SMEM);

    // 0. convert weights to fp16 once
    h2fcopy_kernel<<<(HID * QKV_N / 4) / 256, 256>>>(wqkv, wqkvH);
    h2fcopy_kernel<<<(HID * HID / 4) / 256, 256>>>(wo, woH);
    h2fcopy_kernel<<<(HID * 2 * FFI / 4) / 256, 256>>>(wgu, wguH);
    h2fcopy_kernel<<<(FFI * HID / 4) / 256, 256>>>(wdn, wdnH);

    // 1. h = rmsnorm(x) -> half
    rmsnorm_kernel<<<NT, 256>>>(x, ln1w, hH);
    // 2. qkv = h @ wqkv  (fp32 out)
    f16gemm_kernel<0><<<dim3(QKV_N / 128, NT / 128), 256, GEMM_SMEM>>>(hH, wqkvH, nullptr, qkv, NT, QKV_N, HID);
    // 3. rope (fp32, in place)
    rope_kernel<<<dim3(NT, NH + NKV), 64>>>(qkv, pos);
    // 4. attention (fp16 tensor cores, streamlined softmax) -> half aout
    attn_kernel<<<dim3(SEQ / 64, NH, NB), 256, ATT_SMEM>>>(qkv, aoutH);
    // 5. h1 = x + aout @ wo  (fp32 residual)
    f16gemm_kernel<1><<<dim3(HID / 128, NT / 128), 256, GEMM_SMEM>>>(aoutH, woH, x, h1, NT, HID, HID);
    // 6. h2 = rmsnorm(h1) -> half
    rmsnorm_kernel<<<NT, 256>>>(h1, ln2w, h2H);
    // 7. gu = h2 @ w_gate_up -> half
    f16gemm_kernel<2><<<dim3(2 * FFI / 128, NT / 128), 256, GEMM_SMEM>>>(h2H, wguH, nullptr, guH, NT, 2 * FFI, HID);
    // 8. act = silu(gate)*up (half in) -> half
    silu_kernel<<<(NT * FFI / 4) / 256, 256>>>(guH, actH);
    // 9. out = h1 + act @ w_down  (fp32 out + residual)
    f16gemm_kernel<1><<<dim3(HID / 128, NT / 128), 256, GEMM_SMEM>>>(actH, wdnH, h1, out, NT, HID, FFI);
}

// round 16
// speedup vs baseline: 1.6286x; 1.6286x over previous
#include <cuda_runtime.h>
#include <cuda_fp16.h>
#include <math.h>
#include <stdint.h>

// Problem constants
#define HID   2048
#define NH    16
#define NKV   4
#define HD    128
#define SEQ   1024
#define NB    4
#define NT    4096
#define QKV_N 3072
#define FFI   8192
#define EPS   1e-6f
#define NEGF  (-1e30f)

// ---------------- scratch ----------------
__device__ __half g_hH   [(size_t)NT * HID];
__device__ float  g_qkv  [(size_t)NT * QKV_N];
__device__ __half g_aoutH[(size_t)NT * HID];
__device__ float  g_h1   [(size_t)NT * HID];
__device__ __half g_h2H  [(size_t)NT * HID];
__device__ __half g_guH  [(size_t)NT * 2 * FFI];
__device__ __half g_actH [(size_t)NT * FFI];
__device__ __half g_wqkvH[(size_t)HID * QKV_N];
__device__ __half g_woH  [(size_t)HID * HID];
__device__ __half g_wguH [(size_t)HID * 2 * FFI];
__device__ __half g_wdnH [(size_t)FFI * HID];

// ---------------- helpers ----------------
__device__ __forceinline__ void cp_async16(void* s, const void* g) {
    uint32_t sa = (uint32_t)__cvta_generic_to_shared(s);
    asm volatile("cp.async.cg.shared.global [%0], [%1], 16;\n" :: "r"(sa), "l"(g));
}
__device__ __forceinline__ void ldmx4(uint32_t* r, uint32_t a) {
    asm volatile("ldmatrix.sync.aligned.m8n8.x4.shared.b16 {%0,%1,%2,%3}, [%4];"
        : "=r"(r[0]), "=r"(r[1]), "=r"(r[2]), "=r"(r[3]) : "r"(a));
}
__device__ __forceinline__ void ldmx4t(uint32_t* r, uint32_t a) {
    asm volatile("ldmatrix.sync.aligned.m8n8.x4.trans.shared.b16 {%0,%1,%2,%3}, [%4];"
        : "=r"(r[0]), "=r"(r[1]), "=r"(r[2]), "=r"(r[3]) : "r"(a));
}
__device__ __forceinline__ void mma_f16(float* d, const uint32_t* a, const uint32_t* b) {
    asm volatile(
        "mma.sync.aligned.m16n8k16.row.col.f32.f16.f16.f32 "
        "{%0,%1,%2,%3}, {%4,%5,%6,%7}, {%8,%9}, {%0,%1,%2,%3};\n"
        : "+f"(d[0]), "+f"(d[1]), "+f"(d[2]), "+f"(d[3])
        : "r"(a[0]), "r"(a[1]), "r"(a[2]), "r"(a[3]), "r"(b[0]), "r"(b[1]));
}

// ---------------- fp32 -> fp16 weight copy ----------------
__global__ void __launch_bounds__(256) h2fcopy_kernel(const float* __restrict__ s,
                                                      __half* __restrict__ d) {
    const size_t i = ((size_t)blockIdx.x * 256 + threadIdx.x) * 4;
    const float4 v = *(const float4*)(s + i);
    __half2 p0 = __floats2half2_rn(v.x, v.y);
    __half2 p1 = __floats2half2_rn(v.z, v.w);
    uint2 pk = make_uint2(*(uint32_t*)&p0, *(uint32_t*)&p1);
    *(uint2*)(d + i) = pk;
}

// ---------------- FP16 tensor-core GEMM (round-14 2-stage, static smem) ----------------
// C[M,N] = A[M,K] @ B[K,N].  EPI: 0 = fp32 out, 1 = fp32 out + residual, 2 = half out.
#define APITCH 40
#define BPITCH 136

template <int EPI>
__global__ void __launch_bounds__(256, 2) f16gemm_kernel(const __half* __restrict__ A,
                                                         const __half* __restrict__ B,
                                                         const float* __restrict__ R,
                                                         void* __restrict__ Cv,
                                                         int M, int N, int K) {
    __shared__ __half As[2][128 * APITCH];
    __shared__ __half Bs[2][32 * BPITCH];

    const int tid  = threadIdx.x;
    const int bm   = blockIdx.y * 128;
    const int bn   = blockIdx.x * 128;
    const int lane = tid & 31;
    const int warp = tid >> 5;
    const int g = lane >> 2;
    const int c = lane & 3;
    const int wm = (warp >> 2) * 64;
    const int wn = (warp & 3) * 32;

    float acc[4][4][4];
#pragma unroll
    for (int mi = 0; mi < 4; mi++)
#pragma unroll
        for (int ni = 0; ni < 4; ni++)
#pragma unroll
            for (int r = 0; r < 4; r++) acc[mi][ni][r] = 0.0f;

    const int ntiles = K >> 5;

    auto load_tile = [&](int t, int b) {
        const int kof = t << 5;
#pragma unroll
        for (int j = 0; j < 2; j++) {
            const int ca = tid + j * 256;
            const int row = ca >> 2, kc = ca & 3;
            cp_async16(&As[b][row * APITCH + kc * 8],
                       A + (size_t)(bm + row) * K + kof + kc * 8);
        }
#pragma unroll
        for (int j = 0; j < 2; j++) {
            const int cb = tid + j * 256;
            const int row = cb >> 4, nc = cb & 15;
            cp_async16(&Bs[b][row * BPITCH + nc * 8],
                       B + (size_t)(kof + row) * N + bn + nc * 8);
        }
        asm volatile("cp.async.commit_group;\n");
    };

    load_tile(0, 0);

    const int aq = lane >> 3;
    const int arow = (lane & 7) + (aq & 1) * 8;
    const int acol = (aq >> 1) * 8;
    const int bkrow = (aq & 1) * 8 + (lane & 7);
    const int bncol = (aq >> 1) * 8;

    for (int t = 0; t < ntiles; t++) {
        const int buf = t & 1;
        if (t + 1 < ntiles) {
            load_tile(t + 1, (t + 1) & 1);
            asm volatile("cp.async.wait_group 1;\n");
        } else {
            asm volatile("cp.async.wait_group 0;\n");
        }
        __syncthreads();

        const uint32_t baseA = (uint32_t)__cvta_generic_to_shared(&As[buf][0]);
        const uint32_t baseB = (uint32_t)__cvta_generic_to_shared(&Bs[buf][0]);

#pragma unroll
        for (int ks = 0; ks < 2; ks++) {
            const int k0 = ks << 4;
            uint32_t af[4][4], bf[2][4];
#pragma unroll
            for (int mi = 0; mi < 4; mi++) {
                const int row = wm + mi * 16 + arow;
                ldmx4(af[mi], baseA + (uint32_t)(row * APITCH + k0 + acol) * 2);
            }
#pragma unroll
            for (int n2 = 0; n2 < 2; n2++) {
                const int kk = k0 + bkrow;
                const int nn = wn + n2 * 16 + bncol;
                ldmx4t(bf[n2], baseB + (uint32_t)(kk * BPITCH + nn) * 2);
            }
#pragma unroll
            for (int mi = 0; mi < 4; mi++)
#pragma unroll
                for (int ni = 0; ni < 4; ni++)
                    mma_f16(acc[mi][ni], af[mi], &bf[ni >> 1][(ni & 1) * 2]);
        }
        __syncthreads();
    }

#pragma unroll
    for (int mi = 0; mi < 4; mi++) {
#pragma unroll
        for (int ni = 0; ni < 4; ni++) {
            const int row = bm + wm + mi * 16 + g;
            const int col = bn + wn + ni * 8 + 2 * c;
            const size_t o0 = (size_t)row * N + col;
            const size_t o1 = (size_t)(row + 8) * N + col;
            if (EPI == 2) {
                __half* Ch = (__half*)Cv;
                *(__half2*)(Ch + o0) = __floats2half2_rn(acc[mi][ni][0], acc[mi][ni][1]);
                *(__half2*)(Ch + o1) = __floats2half2_rn(acc[mi][ni][2], acc[mi][ni][3]);
            } else {
                float* C = (float*)Cv;
                float2 v0 = make_float2(acc[mi][ni][0], acc[mi][ni][1]);
                float2 v1 = make_float2(acc[mi][ni][2], acc[mi][ni][3]);
                if (EPI == 1) {
                    float2 r0 = *(const float2*)(R + o0);
                    float2 r1 = *(const float2*)(R + o1);
                    v0.x += r0.x; v0.y += r0.y;
                    v1.x += r1.x; v1.y += r1.y;
                }
                *(float2*)(C + o0) = v0;
                *(float2*)(C + o1) = v1;
            }
        }
    }
}

// ---------------- RMSNorm (fp32 in, half out) ----------------
__global__ void __launch_bounds__(256) rmsnorm_kernel(const float* __restrict__ x,
                                                      const float* __restrict__ w,
                                                      __half* __restrict__ out) {
    const int row = blockIdx.x;
    const int tid = threadIdx.x;
    const float4* xr = (const float4*)(x + (size_t)row * HID);
    const float4* wr = (const float4*)w;

    float4 v0 = xr[tid];
    float4 v1 = xr[tid + 256];
    float ss = v0.x*v0.x + v0.y*v0.y + v0.z*v0.z + v0.w*v0.w
             + v1.x*v1.x + v1.y*v1.y + v1.z*v1.z + v1.w*v1.w;

    __shared__ float red[256];
    red[tid] = ss;
    __syncthreads();
    for (int s = 128; s > 0; s >>= 1) {
        if (tid < s) red[tid] += red[tid + s];
        __syncthreads();
    }
    const float inv = rsqrtf(red[0] * (1.0f / HID) + EPS);

    float4 w0 = wr[tid], w1 = wr[tid + 256];
    __half2* oh = (__half2*)(out + (size_t)row * HID);
    oh[tid * 2]           = __floats2half2_rn(v0.x*inv*w0.x, v0.y*inv*w0.y);
    oh[tid * 2 + 1]       = __floats2half2_rn(v0.z*inv*w0.z, v0.w*inv*w0.w);
    oh[512 + tid * 2]     = __floats2half2_rn(v1.x*inv*w1.x, v1.y*inv*w1.y);
    oh[512 + tid * 2 + 1] = __floats2half2_rn(v1.z*inv*w1.z, v1.w*inv*w1.w);
}

// ---------------- RoPE (fp32 qkv, in place) ----------------
__global__ void rope_kernel(float* __restrict__ qkv, const int* __restrict__ pos) {
    const int t  = blockIdx.x;
    const int hh = blockIdx.y;
    const int i  = threadIdx.x;
    const float p = (float)pos[t & (SEQ - 1)];
    const float inv_freq = powf(10000.0f, -((float)i) / 64.0f);
    float sn, cs;
    sincosf(p * inv_freq, &sn, &cs);
    float* vp = qkv + (size_t)t * QKV_N + hh * HD;
    const float t1 = vp[i];
    const float t2 = vp[i + 64];
    vp[i]      = t1 * cs - t2 * sn;
    vp[i + 64] = t2 * cs + t1 * sn;
}

// ---------------- Flash attention (fp16 tensor-core, fp32 softmax, MUFU exp) --------
#define QP 136
#define KP 72
#define VP 136
#define PP 72
#define ATT_SMEM ((64*QP + 128*KP + 64*VP + 64*PP) * 2 + (64*64 + 3*64) * 4)

__global__ void __launch_bounds__(256) attn_kernel(const float* __restrict__ qkv,
                                                   __half* __restrict__ aout) {
    const int qt = blockIdx.x, h = blockIdx.y, b = blockIdx.z;
    const int kvh = h >> 2;

    extern __shared__ char smb[];
    __half* Qh = (__half*)smb;
    __half* Kh = Qh + 64 * QP;
    __half* Vh = Kh + 128 * KP;
    __half* Ph = Vh + 64 * VP;
    float* Ss   = (float*)(Ph + 64 * PP);
    float* rowm = Ss + 64 * 64;
    float* rowl = rowm + 64;
    float* rowa = rowl + 64;

    const int tid  = threadIdx.x;
    const int lane = tid & 31;
    const int warp = tid >> 5;
    const int wr = warp >> 1, wc = warp & 1;
    const int g = lane >> 2, c = lane & 3;
    const int aq = lane >> 3;
    const int arow = (lane & 7) + (aq & 1) * 8;
    const int acol = (aq >> 1) * 8;
    const int bkrow = (aq & 1) * 8 + (lane & 7);
    const int bncol = (aq >> 1) * 8;
    const int q0 = qt * 64;

    const uint32_t baseQ = (uint32_t)__cvta_generic_to_shared(Qh);
    const uint32_t baseK = (uint32_t)__cvta_generic_to_shared(Kh);
    const uint32_t baseV = (uint32_t)__cvta_generic_to_shared(Vh);
    const uint32_t baseP = (uint32_t)__cvta_generic_to_shared(Ph);

    // load Q tile (fp32 -> half)
    for (int i = tid; i < 64 * 32; i += 256) {
        const int r = i >> 5, c4 = i & 31;
        float4 q = *(const float4*)(qkv + (size_t)(b * SEQ + q0 + r) * QKV_N + h * HD + c4 * 4);
        __half2 p0 = __floats2half2_rn(q.x, q.y);
        __half2 p1 = __floats2half2_rn(q.z, q.w);
        *(uint2*)&Qh[r * QP + c4 * 4] = make_uint2(*(uint32_t*)&p0, *(uint32_t*)&p1);
    }
    if (tid < 64) { rowm[tid] = NEGF; rowl[tid] = 0.0f; }

    float oacc[8][4];
#pragma unroll
    for (int ni = 0; ni < 8; ni++)
#pragma unroll
        for (int r = 0; r < 4; r++) oacc[ni][r] = 0.0f;
    __syncthreads();

    const float scale = 0.0883883476483184f;

    for (int kt = 0; kt <= qt; kt++) {
        const int k0 = kt * 64;
        // K tile: transpose to [d][n] halfs
        for (int i = tid; i < 2048; i += 256) {
            const int r = i & 63, c4 = i >> 6;
            float4 kk = *(const float4*)(qkv + (size_t)(b * SEQ + k0 + r) * QKV_N
                                         + NH * HD + kvh * HD + c4 * 4);
            const int d0 = c4 * 4;
            Kh[(d0 + 0) * KP + r] = __float2half_rn(kk.x);
            Kh[(d0 + 1) * KP + r] = __float2half_rn(kk.y);
            Kh[(d0 + 2) * KP + r] = __float2half_rn(kk.z);
            Kh[(d0 + 3) * KP + r] = __float2half_rn(kk.w);
        }
        // V tile: [kv][d] halfs
        for (int i = tid; i < 2048; i += 256) {
            const int r = i >> 5, c4 = i & 31;
            float4 vv = *(const float4*)(qkv + (size_t)(b * SEQ + k0 + r) * QKV_N
                                         + (NH + NKV) * HD + kvh * HD + c4 * 4);
            __half2 p0 = __floats2half2_rn(vv.x, vv.y);
            __half2 p1 = __floats2half2_rn(vv.z, vv.w);
            *(uint2*)&Vh[r * VP + c4 * 4] = make_uint2(*(uint32_t*)&p0, *(uint32_t*)&p1);
        }
        __syncthreads();

        // S = Q @ K^T
        float sacc[4][4];
#pragma unroll
        for (int ni = 0; ni < 4; ni++)
#pragma unroll
            for (int r = 0; r < 4; r++) sacc[ni][r] = 0.0f;

#pragma unroll
        for (int k16 = 0; k16 < 8; k16++) {
            uint32_t af[4], bf[2][4];
            ldmx4(af, baseQ + (uint32_t)((wr * 16 + arow) * QP + k16 * 16 + acol) * 2);
#pragma unroll
            for (int n2 = 0; n2 < 2; n2++)
                ldmx4t(bf[n2], baseK + (uint32_t)((k16 * 16 + bkrow) * KP
                                                  + wc * 32 + n2 * 16 + bncol) * 2);
#pragma unroll
            for (int ni = 0; ni < 4; ni++)
                mma_f16(sacc[ni], af, &bf[ni >> 1][(ni & 1) * 2]);
        }

        const bool diag = (kt == qt);
        const int srow0 = wr * 16 + g;
#pragma unroll
        for (int ni = 0; ni < 4; ni++) {
            const int col = wc * 32 + ni * 8 + 2 * c;
            float v0 = sacc[ni][0] * scale;
            float v1 = sacc[ni][1] * scale;
            float v2 = sacc[ni][2] * scale;
            float v3 = sacc[ni][3] * scale;
            if (diag) {
                if (srow0 < col)           v0 = NEGF;
                if (srow0 < col + 1)       v1 = NEGF;
                if (srow0 + 8 < col)       v2 = NEGF;
                if (srow0 + 8 < col + 1)   v3 = NEGF;
            }
            Ss[srow0 * 64 + col]           = v0;
            Ss[srow0 * 64 + col + 1]       = v1;
            Ss[(srow0 + 8) * 64 + col]     = v2;
            Ss[(srow0 + 8) * 64 + col + 1] = v3;
        }
        __syncthreads();

        // online softmax: MUFU exp, written directly to Ph (half)
        {
            const int row = tid >> 2, l4 = tid & 3;
            float mx = NEGF;
            for (int cc = l4; cc < 64; cc += 4) mx = fmaxf(mx, Ss[row * 64 + cc]);
            mx = fmaxf(mx, __shfl_xor_sync(0xffffffffu, mx, 1));
            mx = fmaxf(mx, __shfl_xor_sync(0xffffffffu, mx, 2));
            const float mold = rowm[row];
            const float mnew = fmaxf(mold, mx);
            float ls = 0.0f;
            for (int cc = l4; cc < 64; cc += 4) {
                float p = __expf(Ss[row * 64 + cc] - mnew);
                Ph[row * PP + cc] = __float2half_rn(p);
                ls += p;
            }
            ls += __shfl_xor_sync(0xffffffffu, ls, 1);
            ls += __shfl_xor_sync(0xffffffffu, ls, 2);
            if (l4 == 0) {
                const float alpha = __expf(mold - mnew);
                rowa[row] = alpha;
                rowl[row] = rowl[row] * alpha + ls;
                rowm[row] = mnew;
            }
        }
        __syncthreads();

        // O rescale + O += P @ V
        const float al0 = rowa[wr * 16 + g];
        const float al1 = rowa[wr * 16 + g + 8];
#pragma unroll
        for (int ni = 0; ni < 8; ni++) {
            oacc[ni][0] *= al0; oacc[ni][1] *= al0;
            oacc[ni][2] *= al1; oacc[ni][3] *= al1;
        }

#pragma unroll
        for (int k16 = 0; k16 < 4; k16++) {
            uint32_t af[4], bf[4][4];
            ldmx4(af, baseP + (uint32_t)((wr * 16 + arow) * PP + k16 * 16 + acol) * 2);
#pragma unroll
            for (int n2 = 0; n2 < 4; n2++)
                ldmx4t(bf[n2], baseV + (uint32_t)((k16 * 16 + bkrow) * VP
                                                  + wc * 64 + n2 * 16 + bncol) * 2);
#pragma unroll
            for (int ni = 0; ni < 8; ni++)
                mma_f16(oacc[ni], af, &bf[ni >> 1][(ni & 1) * 2]);
        }
        __syncthreads();
    }

    // normalize & write
    const float il0 = 1.0f / rowl[wr * 16 + g];
    const float il1 = 1.0f / rowl[wr * 16 + g + 8];
    const size_t r0g = (size_t)(b * SEQ + q0 + wr * 16 + g) * HID + h * HD;
    const size_t r1g = (size_t)(b * SEQ + q0 + wr * 16 + g + 8) * HID + h * HD;
#pragma unroll
    for (int ni = 0; ni < 8; ni++) {
        const int col = wc * 64 + ni * 8 + 2 * c;
        *(__half2*)(aout + r0g + col) = __floats2half2_rn(oacc[ni][0] * il0, oacc[ni][1] * il0);
        *(__half2*)(aout + r1g + col) = __floats2half2_rn(oacc[ni][2] * il1, oacc[ni][3] * il1);
    }
}

// ---------------- SiLU(gate)*up (half in, half out, MUFU exp) ----------------
__global__ void __launch_bounds__(256) silu_kernel(const __half* __restrict__ gu,
                                                   __half* __restrict__ act) {
    size_t idx = (size_t)blockIdx.x * 256 + threadIdx.x;
    int row = (int)(idx / (FFI / 4));
    int c   = (int)(idx % (FFI / 4));
    uint2 graw = *(const uint2*)(gu + (size_t)row * 2 * FFI + c * 4);
    uint2 uraw = *(const uint2*)(gu + (size_t)row * 2 * FFI + FFI + c * 4);
    float2 g0 = __half22float2(*(__half2*)&graw.x);
    float2 g1 = __half22float2(*(__half2*)&graw.y);
    float2 u0 = __half22float2(*(__half2*)&uraw.x);
    float2 u1 = __half22float2(*(__half2*)&uraw.y);
    float rx = g0.x / (1.0f + __expf(-g0.x)) * u0.x;
    float ry = g0.y / (1.0f + __expf(-g0.y)) * u0.y;
    float rz = g1.x / (1.0f + __expf(-g1.x)) * u1.x;
    float rw = g1.y / (1.0f + __expf(-g1.y)) * u1.y;
    __half2 p0 = __floats2half2_rn(rx, ry);
    __half2 p1 = __floats2half2_rn(rz, rw);
    *(uint2*)(act + (size_t)row * FFI + c * 4) = make_uint2(*(uint32_t*)&p0, *(uint32_t*)&p1);
}

// ---------------- launch ----------------
extern "C" void kernel_launch(void* const* d_in, const int* in_sizes, int n_in,
                              void* d_out, int out_size) {
    const float* x    = (const float*)d_in[0];
    const float* ln1w = (const float*)d_in[1];
    const float* wqkv = (const float*)d_in[2];
    const float* wo   = (const float*)d_in[3];
    const float* ln2w = (const float*)d_in[4];
    const float* wgu  = (const float*)d_in[5];
    const float* wdn  = (const float*)d_in[6];
    const int*   pos  = (const int*)d_in[7];
    float* out = (float*)d_out;

    void *phH, *pqkv, *paoH, *ph1, *ph2H, *pgu, *pactH, *pwq, *pwo, *pwg, *pwd;
    cudaGetSymbolAddress(&phH,   g_hH);
    cudaGetSymbolAddress(&pqkv,  g_qkv);
    cudaGetSymbolAddress(&paoH,  g_aoutH);
    cudaGetSymbolAddress(&ph1,   g_h1);
    cudaGetSymbolAddress(&ph2H,  g_h2H);
    cudaGetSymbolAddress(&pgu,   g_guH);
    cudaGetSymbolAddress(&pactH, g_actH);
    cudaGetSymbolAddress(&pwq,   g_wqkvH);
    cudaGetSymbolAddress(&pwo,   g_woH);
    cudaGetSymbolAddress(&pwg,   g_wguH);
    cudaGetSymbolAddress(&pwd,   g_wdnH);
    __half* hH    = (__half*)phH;
    float*  qkv   = (float*)pqkv;
    __half* aoutH = (__half*)paoH;
    float*  h1    = (float*)ph1;
    __half* h2H   = (__half*)ph2H;
    __half* guH   = (__half*)pgu;
    __half* actH  = (__half*)pactH;
    __half* wqkvH = (__half*)pwq;
    __half* woH   = (__half*)pwo;
    __half* wguH  = (__half*)pwg;
    __half* wdnH  = (__half*)pwd;

    cudaFuncSetAttribute(attn_kernel, cudaFuncAttributeMaxDynamicSharedMemorySize, ATT_SMEM);

    // 0. convert weights to fp16 once
    h2fcopy_kernel<<<(HID * QKV_N / 4) / 256, 256>>>(wqkv, wqkvH);
    h2fcopy_kernel<<<(HID * HID / 4) / 256, 256>>>(wo, woH);
    h2fcopy_kernel<<<(HID * 2 * FFI / 4) / 256, 256>>>(wgu, wguH);
    h2fcopy_kernel<<<(FFI * HID / 4) / 256, 256>>>(wdn, wdnH);

    // 1. h = rmsnorm(x) -> half
    rmsnorm_kernel<<<NT, 256>>>(x, ln1w, hH);
    // 2. qkv = h @ wqkv  (fp32 out)
    f16gemm_kernel<0><<<dim3(QKV_N / 128, NT / 128), 256>>>(hH, wqkvH, nullptr, qkv, NT, QKV_N, HID);
    // 3. rope (fp32, in place)
    rope_kernel<<<dim3(NT, NH + NKV), 64>>>(qkv, pos);
    // 4. attention (fp16 tensor cores) -> half aout
    attn_kernel<<<dim3(SEQ / 64, NH, NB), 256, ATT_SMEM>>>(qkv, aoutH);
    // 5. h1 = x + aout @ wo  (fp32 residual)
    f16gemm_kernel<1><<<dim3(HID / 128, NT / 128), 256>>>(aoutH, woH, x, h1, NT, HID, HID);
    // 6. h2 = rmsnorm(h1) -> half
    rmsnorm_kernel<<<NT, 256>>>(h1, ln2w, h2H);
    // 7. gu = h2 @ w_gate_up -> half
    f16gemm_kernel<2><<<dim3(2 * FFI / 128, NT / 128), 256>>>(h2H, wguH, nullptr, guH, NT, 2 * FFI, HID);
    // 8. act = silu(gate)*up (half in) -> half
    silu_kernel<<<(NT * FFI / 4) / 256, 256>>>(guH, actH);
    // 9. out = h1 + act @ w_down  (fp32 out + residual)
    f16gemm_kernel<1><<<dim3(HID / 128, NT / 128), 256>>>(actH, wdnH, h1, out, NT, HID, FFI);
}